// round 14
// baseline (speedup 1.0000x reference)
#include <cuda_runtime.h>
#include <cuda_fp16.h>
#include <cstdint>

#define DIM   4096
#define N_OBJ 256
#define N_REL 1024
#define EPSF  1e-7f
#define ADJ_MAX 96
#define SUB_MAX 48

// ---------------- scratch (static device arrays; no allocation) ----------------
__device__ float g_h_pred[3][(size_t)N_REL * DIM];
__device__ float g_h_obj[3][(size_t)N_OBJ * DIM];
__device__ float g_cspart[8][DIM];
__device__ __half g_Wh[6ull * DIM * DIM];
__device__ __half g_Xph[(size_t)N_REL * DIM];
__device__ __half g_Xoh[(size_t)N_OBJ * DIM];
__device__ int g_adj[N_REL * ADJ_MAX];
__device__ int g_adj_cnt[N_REL];
__device__ int g_sub_list[N_OBJ * SUB_MAX];
__device__ int g_sub_cnt[N_OBJ];
__device__ int g_obv_list[N_OBJ * SUB_MAX];
__device__ int g_obv_cnt[N_OBJ];

// ---------------- helpers ----------------
__device__ __forceinline__ uint32_t smem_u32(const void* p) {
    uint32_t a;
    asm("{ .reg .u64 t; cvta.to.shared.u64 t, %1; cvt.u32.u64 %0, t; }"
        : "=r"(a) : "l"(p));
    return a;
}
#define CP16(dst, src) \
    asm volatile("cp.async.cg.shared.global [%0], [%1], 16;" :: "r"(dst), "l"(src) : "memory")
#define LDSM4(r, addr) \
    asm volatile("ldmatrix.sync.aligned.m8n8.x4.shared.b16 {%0,%1,%2,%3}, [%4];" \
        : "=r"((r)[0]), "=r"((r)[1]), "=r"((r)[2]), "=r"((r)[3]) : "r"(addr))

__device__ __forceinline__ void mma16816(float* c, const uint32_t* a,
                                         uint32_t b0, uint32_t b1) {
    asm volatile("mma.sync.aligned.m16n8k16.row.col.f32.f16.f16.f32 "
        "{%0,%1,%2,%3}, {%4,%5,%6,%7}, {%8,%9}, {%0,%1,%2,%3};"
        : "+f"(c[0]), "+f"(c[1]), "+f"(c[2]), "+f"(c[3])
        : "r"(a[0]), "r"(a[1]), "r"(a[2]), "r"(a[3]), "r"(b0), "r"(b1));
}

// ---------------- conv (fp32->fp16) + list builds, ONE launch ----------------
#define N4W (6 * DIM * DIM / 4)
#define N4P (N_REL * DIM / 4)
#define N4O (N_OBJ * DIM / 4)
#define N4ALL (N4W + N4P + N4O)
#define CONV_BLOCKS ((N4ALL + 255) / 256)

__global__ void conv_build(const float4* __restrict__ W_all,
                           const float4* __restrict__ pred_feats,
                           const float4* __restrict__ obj_feats,
                           const int* __restrict__ rel_inds)
{
    if (blockIdx.x < CONV_BLOCKS) {
        int i = blockIdx.x * 256 + threadIdx.x;
        const float4* src;
        __half* dst;
        int off;
        if (i < N4W)            { src = W_all;      dst = g_Wh;  off = i; }
        else if (i < N4W + N4P) { src = pred_feats; dst = g_Xph; off = i - N4W; }
        else if (i < N4ALL)     { src = obj_feats;  dst = g_Xoh; off = i - N4W - N4P; }
        else return;
        float4 v = src[off];
        __half2 h01 = __floats2half2_rn(v.x, v.y);
        __half2 h23 = __floats2half2_rn(v.z, v.w);
        uint2 H;
        H.x = *reinterpret_cast<uint32_t*>(&h01);
        H.y = *reinterpret_cast<uint32_t*>(&h23);
        reinterpret_cast<uint2*>(dst)[off] = H;
        return;
    }
    // list-build blocks: warp 0 only
    if (threadIdx.x >= 32) return;
    const int lane = threadIdx.x;
    int bb = blockIdx.x - CONV_BLOCKS;
    if (bb < N_REL) {
        const int r = bb;
        const int my0 = rel_inds[2 * r], my1 = rel_inds[2 * r + 1];
        int base = 0;
        for (int it = 0; it < N_REL / 32; it++) {
            int j = it * 32 + lane;
            int a0 = rel_inds[2 * j], a1 = rel_inds[2 * j + 1];
            bool adj = (j != r) &&
                       ((a0 == my0) | (a1 == my1) | (a0 == my1) | (a1 == my0));
            unsigned m = __ballot_sync(0xffffffffu, adj);
            if (adj) {
                int pos = base + __popc(m & ((1u << lane) - 1u));
                if (pos < ADJ_MAX) g_adj[r * ADJ_MAX + pos] = j;
            }
            base += __popc(m);
        }
        if (lane == 0) g_adj_cnt[r] = (base < ADJ_MAX) ? base : ADJ_MAX;
    } else {
        const int i = bb - N_REL;
        int b0 = 0, b1 = 0;
        for (int it = 0; it < N_REL / 32; it++) {
            int r = it * 32 + lane;
            int s = rel_inds[2 * r], o = rel_inds[2 * r + 1];
            bool f0 = (s == i);
            unsigned m0 = __ballot_sync(0xffffffffu, f0);
            if (f0) {
                int pos = b0 + __popc(m0 & ((1u << lane) - 1u));
                if (pos < SUB_MAX) g_sub_list[i * SUB_MAX + pos] = r;
            }
            b0 += __popc(m0);
            bool f1 = (o == i);
            unsigned m1 = __ballot_sync(0xffffffffu, f1);
            if (f1) {
                int pos = b1 + __popc(m1 & ((1u << lane) - 1u));
                if (pos < SUB_MAX) g_obv_list[i * SUB_MAX + pos] = r;
            }
            b1 += __popc(m1);
        }
        if (lane == 0) {
            g_sub_cnt[i] = (b0 < SUB_MAX) ? b0 : SUB_MAX;
            g_obv_cnt[i] = (b1 < SUB_MAX) ? b1 : SUB_MAX;
        }
    }
}

// ---------------- tensor-core GEMM: H = relu(X @ W^T + b) ----------------
// CTA 128x128, 4 warps, warp tile 64x64, k-chunk 64 (4 MMA phases).
// 3-stage cp.async ring, 1 barrier per chunk, cross-phase fragment pipelining.
#define KC        64
#define PITCH     144                 // 128 B data + 16 pad (9 units, coprime 8)
#define TILEB     (128 * PITCH)       // 18432 B per tile
#define BUFB      (2 * TILEB)         // 36864 B per stage
#define NSTAGE    3
#define SMEM_DYN  (NSTAGE * BUFB)     // 110592 B

__global__ __launch_bounds__(128, 2)
void gemm_tc(const float* __restrict__ b_all)
{
    extern __shared__ char sm_raw[];
    const uint32_t tiles = smem_u32(sm_raw);

    const int tid  = threadIdx.x;
    const int wid  = tid >> 5;
    const int lane = tid & 31;
    const uint32_t lrow = lane & 15;
    const uint32_t lsel = lane >> 4;
    const int wm = (wid & 1) * 64;
    const int wn = (wid >> 1) * 64;

    const int slot = blockIdx.x;
    const int bn   = blockIdx.y * 128;
    int bm, widx;
    const __half* Ah;
    float* H;
    if (slot < 24) {
        int z = slot >> 3; bm = (slot & 7) * 128;
        Ah = g_Xph; H = &g_h_pred[z][0];
        widx = (z == 2) ? 5 : z;
    } else {
        int s = slot - 24; int z = s >> 1; bm = (s & 1) * 128;
        Ah = g_Xoh; H = &g_h_obj[z][0];
        widx = (z == 0) ? 4 : (z + 1);
    }
    const char* gbase[2];
    gbase[0] = (const char*)Ah + (size_t)bm * (DIM * 2);
    gbase[1] = (const char*)(g_Wh + (size_t)widx * DIM * DIM) + (size_t)bn * (DIM * 2);
    const float* bias = b_all + (size_t)widx * DIM + bn;

    float c[4][8][4];
#pragma unroll
    for (int i = 0; i < 4; i++)
#pragma unroll
        for (int j = 0; j < 8; j++)
#pragma unroll
            for (int q = 0; q < 4; q++) c[i][j][q] = 0.f;

    const int NC = DIM / KC;   // 64 chunks
    const int r_ld = tid >> 3, u_ld = tid & 7;   // r_ld 0..15, u_ld 0..7

    auto issue_stage = [&](int kc, int stage) {
        uint32_t dstb = tiles + stage * BUFB;
        size_t koff = (size_t)kc * (KC * 2);
#pragma unroll
        for (int t = 0; t < 2; t++)
#pragma unroll
            for (int rr = 0; rr < 8; rr++) {
                int row = r_ld + rr * 16;
                CP16(dstb + t * TILEB + row * PITCH + u_ld * 16,
                     gbase[t] + (size_t)row * (DIM * 2) + koff + u_ld * 16);
            }
    };

    // prologue: stages 0,1 (chunks 0,1)
    issue_stage(0, 0);
    asm volatile("cp.async.commit_group;" ::: "memory");
    issue_stage(1, 1);
    asm volatile("cp.async.commit_group;" ::: "memory");
    asm volatile("cp.async.wait_group 1;" ::: "memory");
    __syncthreads();

    uint32_t ah[2][4][4], bh[2][4][4];
    // load phase-0 fragments of chunk 0 (buffer 0)
    {
        const uint32_t bufb = tiles;
        const uint32_t uoff = lsel * 16;
#pragma unroll
        for (int jj = 0; jj < 4; jj++)
            LDSM4(bh[0][jj], bufb + TILEB + (wn + 16 * jj + lrow) * PITCH + uoff);
#pragma unroll
        for (int i = 0; i < 4; i++)
            LDSM4(ah[0][i], bufb + (wm + 16 * i + lrow) * PITCH + uoff);
    }

    int curbuf = 0;
    for (int kc = 0; kc < NC; kc++) {
        if (kc + 2 < NC) issue_stage(kc + 2, (kc + 2) % NSTAGE);
        asm volatile("cp.async.commit_group;" ::: "memory");

        const uint32_t bufb = tiles + curbuf * BUFB;
        // phases 0..2: load next phase, MMA current
#pragma unroll
        for (int p = 0; p < 3; p++) {
            const int nxt = (p + 1) & 1, cur = p & 1;
            const uint32_t uoff = ((p + 1) * 2 + lsel) * 16;
#pragma unroll
            for (int jj = 0; jj < 4; jj++)
                LDSM4(bh[nxt][jj], bufb + TILEB + (wn + 16 * jj + lrow) * PITCH + uoff);
#pragma unroll
            for (int i = 0; i < 4; i++)
                LDSM4(ah[nxt][i], bufb + (wm + 16 * i + lrow) * PITCH + uoff);
#pragma unroll
            for (int i = 0; i < 4; i++)
#pragma unroll
                for (int jj = 0; jj < 4; jj++)
#pragma unroll
                    for (int jo = 0; jo < 2; jo++)
                        mma16816(c[i][jj * 2 + jo], ah[cur][i], bh[cur][jj][jo], bh[cur][jj][jo + 2]);
        }

        // chunk kc+1 ready (1 group may remain outstanding)
        asm volatile("cp.async.wait_group 1;" ::: "memory");
        __syncthreads();

        const int nextbuf = (kc + 1) % NSTAGE;
        if (kc + 1 < NC) {
            const uint32_t nb = tiles + nextbuf * BUFB;
            const uint32_t uoff = lsel * 16;   // ks=0 of next chunk -> slot 0
#pragma unroll
            for (int jj = 0; jj < 4; jj++)
                LDSM4(bh[0][jj], nb + TILEB + (wn + 16 * jj + lrow) * PITCH + uoff);
#pragma unroll
            for (int i = 0; i < 4; i++)
                LDSM4(ah[0][i], nb + (wm + 16 * i + lrow) * PITCH + uoff);
        }
        // MMA phase 3 (slot 1) overlaps next-chunk phase-0 loads
#pragma unroll
        for (int i = 0; i < 4; i++)
#pragma unroll
            for (int jj = 0; jj < 4; jj++)
#pragma unroll
                for (int jo = 0; jo < 2; jo++)
                    mma16816(c[i][jj * 2 + jo], ah[1][i], bh[1][jj][jo], bh[1][jj][jo + 2]);

        curbuf = nextbuf;
    }

    // ---- epilogue: bias + relu, direct stores ----
    const int qrow = lane >> 2;
    const int qcol = (lane & 3) * 2;
#pragma unroll
    for (int i = 0; i < 4; i++) {
        int grow0 = bm + wm + 16 * i + qrow;
#pragma unroll
        for (int jb = 0; jb < 8; jb++) {
            int lcol = wn + 8 * jb + qcol;
            int gcol = bn + lcol;
            float b0 = bias[lcol];
            float b1 = bias[lcol + 1];
            float2 v0, v1;
            v0.x = fmaxf(c[i][jb][0] + b0, 0.f);
            v0.y = fmaxf(c[i][jb][1] + b1, 0.f);
            v1.x = fmaxf(c[i][jb][2] + b0, 0.f);
            v1.y = fmaxf(c[i][jb][3] + b1, 0.f);
            *reinterpret_cast<float2*>(H + (size_t)grow0 * DIM + gcol) = v0;
            *reinterpret_cast<float2*>(H + (size_t)(grow0 + 8) * DIM + gcol) = v1;
        }
    }
}

// ---------------- column partial sums of h4 ----------------
__global__ void colsum_part()
{
    int c = blockIdx.x * blockDim.x + threadIdx.x;
    int z = blockIdx.y;
    float s = 0.f;
    for (int r = z * 32; r < z * 32 + 32; r++)
        s += g_h_obj[0][(size_t)r * DIM + c];
    g_cspart[z][c] = s;
}

// ---------------- merged finals (obj rows 0..255, pred rows 256..1279) ----------------
__global__ __launch_bounds__(256)
void finals_kernel(const float* __restrict__ obj_feats,
                   const float* __restrict__ pred_feats,
                   const int*   __restrict__ rel_inds,
                   float* __restrict__ out_obj,
                   float* __restrict__ out_pred)
{
    const int col = blockIdx.x * 1024 + threadIdx.x * 4;
    if (blockIdx.y < N_OBJ) {
        const int i = blockIdx.y;
        const int c0 = g_sub_cnt[i];
        const int c1 = g_obv_cnt[i];

        float4 sum0 = make_float4(0.f, 0.f, 0.f, 0.f);
        float4 sum1 = make_float4(0.f, 0.f, 0.f, 0.f);
        for (int k = 0; k < c0; k++) {
            int r = g_sub_list[i * SUB_MAX + k];
            float4 v = *reinterpret_cast<const float4*>(&g_h_pred[0][(size_t)r * DIM + col]);
            sum0.x += v.x; sum0.y += v.y; sum0.z += v.z; sum0.w += v.w;
        }
        for (int k = 0; k < c1; k++) {
            int r = g_obv_list[i * SUB_MAX + k];
            float4 v = *reinterpret_cast<const float4*>(&g_h_pred[1][(size_t)r * DIM + col]);
            sum1.x += v.x; sum1.y += v.y; sum1.z += v.z; sum1.w += v.w;
        }

        // colsum from partials (folded colsum_red)
        float4 cs = make_float4(0.f, 0.f, 0.f, 0.f);
#pragma unroll
        for (int z = 0; z < 8; z++) {
            float4 p = *reinterpret_cast<const float4*>(&g_cspart[z][col]);
            cs.x += p.x; cs.y += p.y; cs.z += p.z; cs.w += p.w;
        }

        const float inv0 = 1.f / ((float)c0 + EPSF);
        const float inv1 = 1.f / ((float)c1 + EPSF);
        const float invo = 1.f / (255.f + EPSF);
        const float third = 1.f / 3.f;

        float4 h4v = *reinterpret_cast<const float4*>(&g_h_obj[0][(size_t)i * DIM + col]);
        float4 bs  = *reinterpret_cast<const float4*>(&obj_feats[(size_t)i * DIM + col]);
        float4 o;
        o.x = bs.x + ((cs.x - h4v.x) * invo + sum0.x * inv0 + sum1.x * inv1) * third;
        o.y = bs.y + ((cs.y - h4v.y) * invo + sum0.y * inv0 + sum1.y * inv1) * third;
        o.z = bs.z + ((cs.z - h4v.z) * invo + sum0.z * inv0 + sum1.z * inv1) * third;
        o.w = bs.w + ((cs.w - h4v.w) * invo + sum0.w * inv0 + sum1.w * inv1) * third;
        *reinterpret_cast<float4*>(&out_obj[(size_t)i * DIM + col]) = o;
    } else {
        const int r = blockIdx.y - N_OBJ;
        const int my0 = rel_inds[2 * r];
        const int my1 = rel_inds[2 * r + 1];
        const int deg = g_adj_cnt[r];

        float4 sum5 = make_float4(0.f, 0.f, 0.f, 0.f);
        for (int k = 0; k < deg; k++) {
            int j = g_adj[r * ADJ_MAX + k];
            float4 v = *reinterpret_cast<const float4*>(&g_h_pred[2][(size_t)j * DIM + col]);
            sum5.x += v.x; sum5.y += v.y; sum5.z += v.z; sum5.w += v.w;
        }

        const float invd  = 1.f / ((float)deg + EPSF);
        const float inv1e = 1.f / (1.f + EPSF);
        const float third = 1.f / 3.f;

        float4 h2v = *reinterpret_cast<const float4*>(&g_h_obj[1][(size_t)my0 * DIM + col]);
        float4 h3v = *reinterpret_cast<const float4*>(&g_h_obj[2][(size_t)my1 * DIM + col]);
        float4 bs  = *reinterpret_cast<const float4*>(&pred_feats[(size_t)r * DIM + col]);
        float4 o;
        o.x = bs.x + ((h2v.x + h3v.x) * inv1e + sum5.x * invd) * third;
        o.y = bs.y + ((h2v.y + h3v.y) * inv1e + sum5.y * invd) * third;
        o.z = bs.z + ((h2v.z + h3v.z) * inv1e + sum5.z * invd) * third;
        o.w = bs.w + ((h2v.w + h3v.w) * inv1e + sum5.w * invd) * third;
        *reinterpret_cast<float4*>(&out_pred[(size_t)r * DIM + col]) = o;
    }
}

// ---------------- launch ----------------
extern "C" void kernel_launch(void* const* d_in, const int* in_sizes, int n_in,
                              void* d_out, int out_size)
{
    const float* obj_feats  = (const float*)d_in[0];
    const float* pred_feats = (const float*)d_in[1];
    const int*   rel_inds   = (const int*)  d_in[2];
    const float* W_all      = (const float*)d_in[3];
    const float* b_all      = (const float*)d_in[4];

    float* out_obj  = (float*)d_out;
    float* out_pred = (float*)d_out + (size_t)N_OBJ * DIM;

    cudaFuncSetAttribute(gemm_tc, cudaFuncAttributeMaxDynamicSharedMemorySize, SMEM_DYN);

    conv_build<<<CONV_BLOCKS + N_REL + N_OBJ, 256>>>(
        (const float4*)W_all, (const float4*)pred_feats,
        (const float4*)obj_feats, rel_inds);

    gemm_tc<<<dim3(30, 32), 128, SMEM_DYN>>>(b_all);

    colsum_part<<<dim3(DIM / 256, 8), 256>>>();

    finals_kernel<<<dim3(4, N_OBJ + N_REL), 256>>>(
        obj_feats, pred_feats, rel_inds, out_obj, out_pred);
}

// round 15
// speedup vs baseline: 1.4571x; 1.4571x over previous
#include <cuda_runtime.h>
#include <cuda_fp16.h>
#include <cstdint>

#define DIM   4096
#define N_OBJ 256
#define N_REL 1024
#define EPSF  1e-7f
#define ADJ_MAX 96
#define SUB_MAX 48

// ---------------- scratch (static device arrays; no allocation) ----------------
__device__ float g_h_pred[3][(size_t)N_REL * DIM];
__device__ float g_h_obj[3][(size_t)N_OBJ * DIM];
__device__ float g_cspart[8][DIM];
__device__ __half g_Wh[6ull * DIM * DIM];
__device__ __half g_Xph[(size_t)N_REL * DIM];
__device__ __half g_Xoh[(size_t)N_OBJ * DIM];
__device__ int g_adj[N_REL * ADJ_MAX];
__device__ int g_adj_cnt[N_REL];
__device__ int g_sub_list[N_OBJ * SUB_MAX];
__device__ int g_sub_cnt[N_OBJ];
__device__ int g_obv_list[N_OBJ * SUB_MAX];
__device__ int g_obv_cnt[N_OBJ];

// ---------------- helpers ----------------
__device__ __forceinline__ uint32_t smem_u32(const void* p) {
    uint32_t a;
    asm("{ .reg .u64 t; cvta.to.shared.u64 t, %1; cvt.u32.u64 %0, t; }"
        : "=r"(a) : "l"(p));
    return a;
}
#define CP16(dst, src) \
    asm volatile("cp.async.cg.shared.global [%0], [%1], 16;" :: "r"(dst), "l"(src) : "memory")
#define LDSM4(r, addr) \
    asm volatile("ldmatrix.sync.aligned.m8n8.x4.shared.b16 {%0,%1,%2,%3}, [%4];" \
        : "=r"((r)[0]), "=r"((r)[1]), "=r"((r)[2]), "=r"((r)[3]) : "r"(addr))

__device__ __forceinline__ void mma16816(float* c, const uint32_t* a,
                                         uint32_t b0, uint32_t b1) {
    asm volatile("mma.sync.aligned.m16n8k16.row.col.f32.f16.f16.f32 "
        "{%0,%1,%2,%3}, {%4,%5,%6,%7}, {%8,%9}, {%0,%1,%2,%3};"
        : "+f"(c[0]), "+f"(c[1]), "+f"(c[2]), "+f"(c[3])
        : "r"(a[0]), "r"(a[1]), "r"(a[2]), "r"(a[3]), "r"(b0), "r"(b1));
}

// ---------------- conv (fp32->fp16) + list builds, ONE launch ----------------
#define N4W (6 * DIM * DIM / 4)
#define N4P (N_REL * DIM / 4)
#define N4O (N_OBJ * DIM / 4)
#define N4ALL (N4W + N4P + N4O)
#define CONV_BLOCKS ((N4ALL + 255) / 256)

__global__ void conv_build(const float4* __restrict__ W_all,
                           const float4* __restrict__ pred_feats,
                           const float4* __restrict__ obj_feats,
                           const int* __restrict__ rel_inds)
{
    if (blockIdx.x < CONV_BLOCKS) {
        int i = blockIdx.x * 256 + threadIdx.x;
        const float4* src;
        __half* dst;
        int off;
        if (i < N4W)            { src = W_all;      dst = g_Wh;  off = i; }
        else if (i < N4W + N4P) { src = pred_feats; dst = g_Xph; off = i - N4W; }
        else if (i < N4ALL)     { src = obj_feats;  dst = g_Xoh; off = i - N4W - N4P; }
        else return;
        float4 v = src[off];
        __half2 h01 = __floats2half2_rn(v.x, v.y);
        __half2 h23 = __floats2half2_rn(v.z, v.w);
        uint2 H;
        H.x = *reinterpret_cast<uint32_t*>(&h01);
        H.y = *reinterpret_cast<uint32_t*>(&h23);
        reinterpret_cast<uint2*>(dst)[off] = H;
        return;
    }
    // list-build blocks: warp 0 only
    if (threadIdx.x >= 32) return;
    const int lane = threadIdx.x;
    int bb = blockIdx.x - CONV_BLOCKS;
    if (bb < N_REL) {
        const int r = bb;
        const int my0 = rel_inds[2 * r], my1 = rel_inds[2 * r + 1];
        int base = 0;
        for (int it = 0; it < N_REL / 32; it++) {
            int j = it * 32 + lane;
            int a0 = rel_inds[2 * j], a1 = rel_inds[2 * j + 1];
            bool adj = (j != r) &&
                       ((a0 == my0) | (a1 == my1) | (a0 == my1) | (a1 == my0));
            unsigned m = __ballot_sync(0xffffffffu, adj);
            if (adj) {
                int pos = base + __popc(m & ((1u << lane) - 1u));
                if (pos < ADJ_MAX) g_adj[r * ADJ_MAX + pos] = j;
            }
            base += __popc(m);
        }
        if (lane == 0) g_adj_cnt[r] = (base < ADJ_MAX) ? base : ADJ_MAX;
    } else {
        const int i = bb - N_REL;
        int b0 = 0, b1 = 0;
        for (int it = 0; it < N_REL / 32; it++) {
            int r = it * 32 + lane;
            int s = rel_inds[2 * r], o = rel_inds[2 * r + 1];
            bool f0 = (s == i);
            unsigned m0 = __ballot_sync(0xffffffffu, f0);
            if (f0) {
                int pos = b0 + __popc(m0 & ((1u << lane) - 1u));
                if (pos < SUB_MAX) g_sub_list[i * SUB_MAX + pos] = r;
            }
            b0 += __popc(m0);
            bool f1 = (o == i);
            unsigned m1 = __ballot_sync(0xffffffffu, f1);
            if (f1) {
                int pos = b1 + __popc(m1 & ((1u << lane) - 1u));
                if (pos < SUB_MAX) g_obv_list[i * SUB_MAX + pos] = r;
            }
            b1 += __popc(m1);
        }
        if (lane == 0) {
            g_sub_cnt[i] = (b0 < SUB_MAX) ? b0 : SUB_MAX;
            g_obv_cnt[i] = (b1 < SUB_MAX) ? b1 : SUB_MAX;
        }
    }
}

// ---------------- tensor-core GEMM: H = relu(X @ W^T + b) ----------------
// R12 config: CTA 128x128, 4 warps, warp tile 64x64, k-chunk 32.
// 4-stage cp.async ring (wait_group 2), cross-phase fragment pipelining,
// 2 CTAs/SM (80 KB smem/CTA).
#define KC        32
#define PITCH     80
#define TILEB     (128 * PITCH)       // 10240 B per tile
#define BUFB      (2 * TILEB)         // 20480 B per stage
#define NSTAGE    4
#define SMEM_DYN  (NSTAGE * BUFB)     // 81920 B

__global__ __launch_bounds__(128, 2)
void gemm_tc(const float* __restrict__ b_all)
{
    extern __shared__ char sm_raw[];
    const uint32_t tiles = smem_u32(sm_raw);

    const int tid  = threadIdx.x;
    const int wid  = tid >> 5;
    const int lane = tid & 31;
    const uint32_t lrow = lane & 15;
    const uint32_t lsel = lane >> 4;
    const int wm = (wid & 1) * 64;
    const int wn = (wid >> 1) * 64;

    const int slot = blockIdx.x;
    const int bn   = blockIdx.y * 128;
    int bm, widx;
    const __half* Ah;
    float* H;
    if (slot < 24) {
        int z = slot >> 3; bm = (slot & 7) * 128;
        Ah = g_Xph; H = &g_h_pred[z][0];
        widx = (z == 2) ? 5 : z;
    } else {
        int s = slot - 24; int z = s >> 1; bm = (s & 1) * 128;
        Ah = g_Xoh; H = &g_h_obj[z][0];
        widx = (z == 0) ? 4 : (z + 1);
    }
    const char* gbase[2];
    gbase[0] = (const char*)Ah + (size_t)bm * (DIM * 2);
    gbase[1] = (const char*)(g_Wh + (size_t)widx * DIM * DIM) + (size_t)bn * (DIM * 2);
    const float* bias = b_all + (size_t)widx * DIM + bn;

    float c[4][8][4];
#pragma unroll
    for (int i = 0; i < 4; i++)
#pragma unroll
        for (int j = 0; j < 8; j++)
#pragma unroll
            for (int q = 0; q < 4; q++) c[i][j][q] = 0.f;

    const int NC = DIM / KC;   // 128 chunks
    const int r_ld = tid >> 2, u_ld = tid & 3;

    auto issue_stage = [&](int kc, int stage) {
        uint32_t dstb = tiles + stage * BUFB;
        size_t koff = (size_t)kc * (KC * 2);
#pragma unroll
        for (int t = 0; t < 2; t++)
#pragma unroll
            for (int rr = 0; rr < 4; rr++) {
                int row = r_ld + rr * 32;
                CP16(dstb + t * TILEB + row * PITCH + u_ld * 16,
                     gbase[t] + (size_t)row * (DIM * 2) + koff + u_ld * 16);
            }
    };

    // prologue: stages 0,1,2
    issue_stage(0, 0);
    asm volatile("cp.async.commit_group;" ::: "memory");
    issue_stage(1, 1);
    asm volatile("cp.async.commit_group;" ::: "memory");
    issue_stage(2, 2);
    asm volatile("cp.async.commit_group;" ::: "memory");
    asm volatile("cp.async.wait_group 2;" ::: "memory");
    __syncthreads();

    uint32_t ah[2][4][4], bh[2][4][4];
    // load phase-0 fragments of chunk 0 (buffer 0)
    {
        const uint32_t bufb = tiles;
        const uint32_t uoff = lsel * 16;   // ks=0
#pragma unroll
        for (int jj = 0; jj < 4; jj++)
            LDSM4(bh[0][jj], bufb + TILEB + (wn + 16 * jj + lrow) * PITCH + uoff);
#pragma unroll
        for (int i = 0; i < 4; i++)
            LDSM4(ah[0][i], bufb + (wm + 16 * i + lrow) * PITCH + uoff);
    }

    int curbuf = 0;
    for (int kc = 0; kc < NC; kc++) {
        if (kc + 3 < NC) issue_stage(kc + 3, (kc + 3) % NSTAGE);
        asm volatile("cp.async.commit_group;" ::: "memory");

        const uint32_t bufb = tiles + curbuf * BUFB;
        // load phase-1 fragments (overlaps MMA of phase 0)
        {
            const uint32_t uoff = (2 + lsel) * 16;   // ks=1
#pragma unroll
            for (int jj = 0; jj < 4; jj++)
                LDSM4(bh[1][jj], bufb + TILEB + (wn + 16 * jj + lrow) * PITCH + uoff);
#pragma unroll
            for (int i = 0; i < 4; i++)
                LDSM4(ah[1][i], bufb + (wm + 16 * i + lrow) * PITCH + uoff);
        }
        // MMA phase 0
#pragma unroll
        for (int i = 0; i < 4; i++)
#pragma unroll
            for (int jj = 0; jj < 4; jj++)
#pragma unroll
                for (int jo = 0; jo < 2; jo++)
                    mma16816(c[i][jj * 2 + jo], ah[0][i], bh[0][jj][jo], bh[0][jj][jo + 2]);

        asm volatile("cp.async.wait_group 2;" ::: "memory");
        __syncthreads();

        const int nextbuf = (kc + 1) % NSTAGE;
        if (kc + 1 < NC) {
            const uint32_t nb = tiles + nextbuf * BUFB;
            const uint32_t uoff = lsel * 16;   // ks=0 of next chunk
#pragma unroll
            for (int jj = 0; jj < 4; jj++)
                LDSM4(bh[0][jj], nb + TILEB + (wn + 16 * jj + lrow) * PITCH + uoff);
#pragma unroll
            for (int i = 0; i < 4; i++)
                LDSM4(ah[0][i], nb + (wm + 16 * i + lrow) * PITCH + uoff);
        }
        // MMA phase 1 (overlaps next-chunk phase-0 loads)
#pragma unroll
        for (int i = 0; i < 4; i++)
#pragma unroll
            for (int jj = 0; jj < 4; jj++)
#pragma unroll
                for (int jo = 0; jo < 2; jo++)
                    mma16816(c[i][jj * 2 + jo], ah[1][i], bh[1][jj][jo], bh[1][jj][jo + 2]);

        curbuf = nextbuf;
    }

    // ---- epilogue: bias + relu, direct stores ----
    const int qrow = lane >> 2;
    const int qcol = (lane & 3) * 2;
#pragma unroll
    for (int i = 0; i < 4; i++) {
        int grow0 = bm + wm + 16 * i + qrow;
#pragma unroll
        for (int jb = 0; jb < 8; jb++) {
            int lcol = wn + 8 * jb + qcol;
            int gcol = bn + lcol;
            float b0 = bias[lcol];
            float b1 = bias[lcol + 1];
            float2 v0, v1;
            v0.x = fmaxf(c[i][jb][0] + b0, 0.f);
            v0.y = fmaxf(c[i][jb][1] + b1, 0.f);
            v1.x = fmaxf(c[i][jb][2] + b0, 0.f);
            v1.y = fmaxf(c[i][jb][3] + b1, 0.f);
            *reinterpret_cast<float2*>(H + (size_t)grow0 * DIM + gcol) = v0;
            *reinterpret_cast<float2*>(H + (size_t)(grow0 + 8) * DIM + gcol) = v1;
        }
    }
}

// ---------------- column partial sums of h4 ----------------
__global__ void colsum_part()
{
    int c = blockIdx.x * blockDim.x + threadIdx.x;
    int z = blockIdx.y;
    float s = 0.f;
    for (int r = z * 32; r < z * 32 + 32; r++)
        s += g_h_obj[0][(size_t)r * DIM + c];
    g_cspart[z][c] = s;
}

// ---------------- merged finals (obj rows 0..255, pred rows 256..1279) ----------------
__global__ __launch_bounds__(256)
void finals_kernel(const float* __restrict__ obj_feats,
                   const float* __restrict__ pred_feats,
                   const int*   __restrict__ rel_inds,
                   float* __restrict__ out_obj,
                   float* __restrict__ out_pred)
{
    const int col = blockIdx.x * 1024 + threadIdx.x * 4;
    if (blockIdx.y < N_OBJ) {
        const int i = blockIdx.y;
        const int c0 = g_sub_cnt[i];
        const int c1 = g_obv_cnt[i];

        float4 sum0 = make_float4(0.f, 0.f, 0.f, 0.f);
        float4 sum1 = make_float4(0.f, 0.f, 0.f, 0.f);
        for (int k = 0; k < c0; k++) {
            int r = g_sub_list[i * SUB_MAX + k];
            float4 v = *reinterpret_cast<const float4*>(&g_h_pred[0][(size_t)r * DIM + col]);
            sum0.x += v.x; sum0.y += v.y; sum0.z += v.z; sum0.w += v.w;
        }
        for (int k = 0; k < c1; k++) {
            int r = g_obv_list[i * SUB_MAX + k];
            float4 v = *reinterpret_cast<const float4*>(&g_h_pred[1][(size_t)r * DIM + col]);
            sum1.x += v.x; sum1.y += v.y; sum1.z += v.z; sum1.w += v.w;
        }

        float4 cs = make_float4(0.f, 0.f, 0.f, 0.f);
#pragma unroll
        for (int z = 0; z < 8; z++) {
            float4 p = *reinterpret_cast<const float4*>(&g_cspart[z][col]);
            cs.x += p.x; cs.y += p.y; cs.z += p.z; cs.w += p.w;
        }

        const float inv0 = 1.f / ((float)c0 + EPSF);
        const float inv1 = 1.f / ((float)c1 + EPSF);
        const float invo = 1.f / (255.f + EPSF);
        const float third = 1.f / 3.f;

        float4 h4v = *reinterpret_cast<const float4*>(&g_h_obj[0][(size_t)i * DIM + col]);
        float4 bs  = *reinterpret_cast<const float4*>(&obj_feats[(size_t)i * DIM + col]);
        float4 o;
        o.x = bs.x + ((cs.x - h4v.x) * invo + sum0.x * inv0 + sum1.x * inv1) * third;
        o.y = bs.y + ((cs.y - h4v.y) * invo + sum0.y * inv0 + sum1.y * inv1) * third;
        o.z = bs.z + ((cs.z - h4v.z) * invo + sum0.z * inv0 + sum1.z * inv1) * third;
        o.w = bs.w + ((cs.w - h4v.w) * invo + sum0.w * inv0 + sum1.w * inv1) * third;
        *reinterpret_cast<float4*>(&out_obj[(size_t)i * DIM + col]) = o;
    } else {
        const int r = blockIdx.y - N_OBJ;
        const int my0 = rel_inds[2 * r];
        const int my1 = rel_inds[2 * r + 1];
        const int deg = g_adj_cnt[r];

        float4 sum5 = make_float4(0.f, 0.f, 0.f, 0.f);
        for (int k = 0; k < deg; k++) {
            int j = g_adj[r * ADJ_MAX + k];
            float4 v = *reinterpret_cast<const float4*>(&g_h_pred[2][(size_t)j * DIM + col]);
            sum5.x += v.x; sum5.y += v.y; sum5.z += v.z; sum5.w += v.w;
        }

        const float invd  = 1.f / ((float)deg + EPSF);
        const float inv1e = 1.f / (1.f + EPSF);
        const float third = 1.f / 3.f;

        float4 h2v = *reinterpret_cast<const float4*>(&g_h_obj[1][(size_t)my0 * DIM + col]);
        float4 h3v = *reinterpret_cast<const float4*>(&g_h_obj[2][(size_t)my1 * DIM + col]);
        float4 bs  = *reinterpret_cast<const float4*>(&pred_feats[(size_t)r * DIM + col]);
        float4 o;
        o.x = bs.x + ((h2v.x + h3v.x) * inv1e + sum5.x * invd) * third;
        o.y = bs.y + ((h2v.y + h3v.y) * inv1e + sum5.y * invd) * third;
        o.z = bs.z + ((h2v.z + h3v.z) * inv1e + sum5.z * invd) * third;
        o.w = bs.w + ((h2v.w + h3v.w) * inv1e + sum5.w * invd) * third;
        *reinterpret_cast<float4*>(&out_pred[(size_t)r * DIM + col]) = o;
    }
}

// ---------------- launch ----------------
extern "C" void kernel_launch(void* const* d_in, const int* in_sizes, int n_in,
                              void* d_out, int out_size)
{
    const float* obj_feats  = (const float*)d_in[0];
    const float* pred_feats = (const float*)d_in[1];
    const int*   rel_inds   = (const int*)  d_in[2];
    const float* W_all      = (const float*)d_in[3];
    const float* b_all      = (const float*)d_in[4];

    float* out_obj  = (float*)d_out;
    float* out_pred = (float*)d_out + (size_t)N_OBJ * DIM;

    cudaFuncSetAttribute(gemm_tc, cudaFuncAttributeMaxDynamicSharedMemorySize, SMEM_DYN);

    conv_build<<<CONV_BLOCKS + N_REL + N_OBJ, 256>>>(
        (const float4*)W_all, (const float4*)pred_feats,
        (const float4*)obj_feats, rel_inds);

    gemm_tc<<<dim3(30, 32), 128, SMEM_DYN>>>(b_all);

    colsum_part<<<dim3(DIM / 256, 8), 256>>>();

    finals_kernel<<<dim3(4, N_OBJ + N_REL), 256>>>(
        obj_feats, pred_feats, rel_inds, out_obj, out_pred);
}